// round 14
// baseline (speedup 1.0000x reference)
#include <cuda_runtime.h>
#include <cuda_bf16.h>
#include <cuda_fp16.h>

// Problem constants (fixed by dataset): B=16, C=80, D=1024, S=14 (P=196)
#define BB 16
#define CC 80
#define DD 1024
#define PP 196
#define PT 4            // pixels per block in phase 1 (2 warps/pixel, class-split)
#define SSTRIDE 1032    // padded smem stride for f32 img staging
#define CH 4            // classes per half per chunk (8 word rows staged)

// Scratch (no allocation allowed -> device globals)
__device__ float g_imgT[BB * PP * DD];        // [b][p][d]  transposed img, 12.8MB
__device__ float g_scores[BB * CC * PP];      // [b][c][p]
__device__ float g_coef[BB * PP * CC];        // [b][p][c]

typedef unsigned u32;
typedef unsigned long long ull;

__device__ __forceinline__ u32 hmul2(u32 a, u32 b) {
    u32 r; asm("mul.rn.f16x2 %0, %1, %2;" : "=r"(r) : "r"(a), "r"(b)); return r;
}
__device__ __forceinline__ u32 hadd2(u32 a, u32 b) {
    u32 r; asm("add.rn.f16x2 %0, %1, %2;" : "=r"(r) : "r"(a), "r"(b)); return r;
}
__device__ __forceinline__ u32 htanh2(u32 a) {
    u32 r; asm("tanh.approx.f16x2 %0, %1;" : "=r"(r) : "r"(a)); return r;
}
// pack {hi -> upper 16, lo -> lower 16}
__device__ __forceinline__ u32 pack_f16x2(float hi, float lo) {
    u32 r; asm("cvt.rn.f16x2.f32 %0, %1, %2;" : "=r"(r) : "f"(hi), "f"(lo)); return r;
}
__device__ __forceinline__ float2 unpack_f16x2(u32 h) {
    float lo, hi;
    asm("{\n\t.reg .f16 l, u;\n\t"
        "mov.b32 {l, u}, %2;\n\t"
        "cvt.f32.f16 %0, l;\n\t"
        "cvt.f32.f16 %1, u;\n\t}"
        : "=f"(lo), "=f"(hi) : "r"(h));
    return make_float2(lo, hi);
}
__device__ __forceinline__ ull pack2(float a, float b) {
    ull r; asm("mov.b64 %0, {%1, %2};" : "=l"(r) : "f"(a), "f"(b)); return r;
}
__device__ __forceinline__ ull fma2(ull a, ull b, ull c) {
    ull d; asm("fma.rn.f32x2 %0, %1, %2, %3;" : "=l"(d) : "l"(a), "l"(b), "l"(c)); return d;
}
__device__ __forceinline__ float2 unpack2(ull a) {
    float lo, hi; asm("mov.b64 {%0, %1}, %2;" : "=f"(lo), "=f"(hi) : "l"(a));
    return make_float2(lo, hi);
}

// smem layout for phase 1 (floats):
//   region A [0 .. PT*SSTRIDE)     : f32 img staging, later f16x2 word chunks
//                                    (8 rows x 512 u32 = 16KB <= 16.5KB)
//   region B [PT*SSTRIDE .. +PT*512): persistent f16x2 img tile [PT][512] u32
#define SMEM1_BYTES ((PT * SSTRIDE + PT * (DD / 2)) * 4)

// ---------------------------------------------------------------------------
// Phase 1: scores[b,c,p] = sum_d tanh(img[b,d,p]*word[c,d]) * w[d]
// Class-split: warp = (pixel, class-half). 784 blocks x 8 warps = 6272 warps
// (2x the warp-per-pixel ceiling) -> occupancy ~60%, hiding LDS/MUFU latency.
// All-fp16 inner loop (HMUL2 -> tanh.approx.f16x2 -> HMUL2 -> HADD2 tree).
// Also writes imgT[b,p,d] (f32, coalesced) for phase 3.
// grid (49, 16), block 256 = 4 pixels x 2 halves.
// ---------------------------------------------------------------------------
__global__ __launch_bounds__(256, 5) void scores_kernel(
    const float* __restrict__ img,      // [B][D][P]
    const float* __restrict__ word,     // [C][D]
    const float* __restrict__ faw)      // [D]
{
    extern __shared__ float sm[];
    float* smA = sm;                                // staging / word chunks
    u32*   smI = (u32*)(sm + PT * SSTRIDE);         // 8KB f16x2 img tile

    const int b  = blockIdx.y;
    const int p0 = blockIdx.x * PT;
    const int tid = threadIdx.x;

    // --- Stage img tile (f32): [PT pixels][D] -> region A (196 = 49*4, no tail)
    const float* imgb = img + (size_t)b * DD * PP;
    for (int i = tid; i < PT * DD; i += 256) {
        int p = i & (PT - 1), d = i >> 2;
        smA[p * SSTRIDE + d] = imgb[d * PP + p0 + p];
    }
    __syncthreads();

    const int lane = tid & 31, w = tid >> 5;
    const int pw = w >> 1;              // pixel within block (0..3)
    const int h  = w & 1;               // class half (0..1)
    const int p  = p0 + pw;

    // Two warps per pixel: warp h converts d-half h to f16x2 tile + emits imgT.
    // Each thread also caches fc_a_w for ITS 32 d's (full range, both halves same).
    u32 wv2[16];
    {
        const float4* rowA = (const float4*)&smA[pw * SSTRIDE];
        const float4* faw4 = (const float4*)faw;
        float4* outT = (float4*)(g_imgT + ((size_t)b * PP + p) * DD);
        u32* rowI = smI + pw * (DD / 2);
        #pragma unroll
        for (int k = 0; k < 4; k++) {
            int f4 = h * 128 + lane + 32 * k;        // float4 index 0..255
            float4 v = rowA[f4];
            outT[f4] = v;
            rowI[2 * f4]     = pack_f16x2(v.y, v.x);
            rowI[2 * f4 + 1] = pack_f16x2(v.w, v.z);
        }
        #pragma unroll
        for (int k = 0; k < 4; k++) {
            int f4 = 2 * (lane + 32 * k);            // two float4 per uint4
            float4 q0 = faw4[f4], q1 = faw4[f4 + 1];
            wv2[4*k+0] = pack_f16x2(q0.y, q0.x);
            wv2[4*k+1] = pack_f16x2(q0.w, q0.z);
            wv2[4*k+2] = pack_f16x2(q1.y, q1.x);
            wv2[4*k+3] = pack_f16x2(q1.w, q1.z);
        }
    }
    __syncthreads();   // f32 staging dead; region A now belongs to word chunks

    float* scb = g_scores + ((size_t)b * CC + h * 40) * PP + p;
    const float4* word4 = (const float4*)word;
    u32* smw = (u32*)smA;
    const uint4* is = (const uint4*)(smI + pw * (DD / 2));

    #pragma unroll 1
    for (int c0 = 0; c0 < 40; c0 += CH) {
        // Cooperative load+convert of 2*CH word rows to f16x2 (16KB):
        // slots 0..3 = classes c0..c0+3 (half 0), slots 4..7 = 40+c0.. (half 1)
        #pragma unroll
        for (int i = 0; i < 8; i++) {                // 2048 uint2 / 256 threads
            int idx = tid + 256 * i;
            int s = idx >> 8, j = idx & 255;         // slot, float4-within-row
            int grow = c0 + s + ((s >= CH) ? (40 - CH) : 0);
            float4 v = word4[grow * (DD / 4) + j];
            ((uint2*)smw)[idx] = make_uint2(pack_f16x2(v.y, v.x), pack_f16x2(v.w, v.z));
        }
        __syncthreads();

        #pragma unroll 1
        for (int cc = 0; cc < CH; cc++) {
            const uint4* ws = (const uint4*)(smw + (h * CH + cc) * (DD / 2));
            u32 accA = 0u, accB = 0u;                // two f16x2 accumulators
            #pragma unroll
            for (int k = 0; k < 4; k++) {
                uint4 wd = ws[lane + 32 * k];        // 8 d's of word (f16x2)
                uint4 iv = is[lane + 32 * k];        // 8 d's of img  (f16x2)
                u32 t0 = htanh2(hmul2(iv.x, wd.x));
                u32 t1 = htanh2(hmul2(iv.y, wd.y));
                u32 t2 = htanh2(hmul2(iv.z, wd.z));
                u32 t3 = htanh2(hmul2(iv.w, wd.w));
                u32 s2 = hadd2(hadd2(hmul2(t0, wv2[4*k+0]), hmul2(t1, wv2[4*k+1])),
                               hadd2(hmul2(t2, wv2[4*k+2]), hmul2(t3, wv2[4*k+3])));
                if (k & 1) accB = hadd2(accB, s2); else accA = hadd2(accA, s2);
            }
            float2 fa = unpack_f16x2(accA);
            float2 fb = unpack_f16x2(accB);
            float acc = (fa.x + fa.y) + (fb.x + fb.y);
            #pragma unroll
            for (int o = 16; o; o >>= 1)
                acc += __shfl_xor_sync(0xFFFFFFFFu, acc, o);
            if (lane == 0)
                scb[(c0 + cc) * PP] = acc;
            // fc_a_b is a uniform shift over spatial scores -> softmax-invariant
        }
        __syncthreads();   // chunk consumed; safe to overwrite
    }
}

// ---------------------------------------------------------------------------
// Phase 2: coef[b,p,c] = softmax over p of scores[b,c,p]. One warp per (b,c).
// ---------------------------------------------------------------------------
__global__ __launch_bounds__(256) void softmax_kernel()
{
    const int gw   = blockIdx.x * 8 + (threadIdx.x >> 5);   // 0..1279
    const int lane = threadIdx.x & 31;
    const int b = gw / CC, c = gw % CC;

    const float* sc = g_scores + ((size_t)b * CC + c) * PP;
    float v[7];
    float mx = -1e30f;
    #pragma unroll
    for (int k = 0; k < 7; k++) {
        int p = lane + 32 * k;
        v[k] = (p < PP) ? sc[p] : -1e30f;
        mx = fmaxf(mx, v[k]);
    }
    #pragma unroll
    for (int o = 16; o; o >>= 1)
        mx = fmaxf(mx, __shfl_xor_sync(0xFFFFFFFFu, mx, o));

    float sum = 0.f;
    #pragma unroll
    for (int k = 0; k < 7; k++) {
        v[k] = __expf(v[k] - mx);      // invalid p -> exp(-inf) = 0
        sum += v[k];
    }
    #pragma unroll
    for (int o = 16; o; o >>= 1)
        sum += __shfl_xor_sync(0xFFFFFFFFu, sum, o);

    float inv = 1.0f / sum;
    #pragma unroll
    for (int k = 0; k < 7; k++) {
        int p = lane + 32 * k;
        if (p < PP)
            g_coef[((size_t)b * PP + p) * CC + c] = v[k] * inv;
    }
}

// ---------------------------------------------------------------------------
// Phase 3: out[b,c,d] = sum_p coef[b,p,c] * imgT[b,p,d]
// grid (8 d-tiles of 128, 16 b), block 256 (163KB dyn smem, 1 block/SM).
// Thread tile: 10 c x 4 d, packed fma.rn.f32x2 (pairs over c).
// ---------------------------------------------------------------------------
__global__ __launch_bounds__(256) void out_kernel(float* __restrict__ out)
{
    extern __shared__ float sm[];
    float* img_s  = sm;                 // [196][128]
    float* coef_s = sm + PP * 128;      // [196][80]

    const int b  = blockIdx.y;
    const int d0 = blockIdx.x * 128;
    const int tid = threadIdx.x;

    const float* imgT = g_imgT + (size_t)b * PP * DD;
    for (int i = tid; i < PP * 32; i += 256) {   // 196 * 128/4 float4s
        int pp = i >> 5, j = i & 31;
        ((float4*)img_s)[pp * 32 + j] = *(const float4*)(imgT + (size_t)pp * DD + d0 + 4 * j);
    }
    const float4* coefb = (const float4*)(g_coef + (size_t)b * PP * CC);
    for (int i = tid; i < PP * 20; i += 256)     // 196 * 80/4 float4s
        ((float4*)coef_s)[i] = coefb[i];
    __syncthreads();

    const int dg = tid & 31;            // lanes over d-quads (conflict-free LDS.128)
    const int cg = tid >> 5;            // warp = c-group (broadcast coef LDS.64)

    ull acc[5][4];
    #pragma unroll
    for (int j = 0; j < 5; j++)
        #pragma unroll
        for (int dd = 0; dd < 4; dd++) acc[j][dd] = 0ull;

    #pragma unroll 2
    for (int p = 0; p < PP; p++) {
        float4 iv = ((const float4*)img_s)[p * 32 + dg];
        ull ix = pack2(iv.x, iv.x);
        ull iy = pack2(iv.y, iv.y);
        ull iz = pack2(iv.z, iv.z);
        ull iw = pack2(iv.w, iv.w);
        const ull* cpr = (const ull*)(coef_s + p * CC + cg * 10);
        #pragma unroll
        for (int j = 0; j < 5; j++) {
            ull cc = cpr[j];            // (coef[c], coef[c+1])
            acc[j][0] = fma2(cc, ix, acc[j][0]);
            acc[j][1] = fma2(cc, iy, acc[j][1]);
            acc[j][2] = fma2(cc, iz, acc[j][2]);
            acc[j][3] = fma2(cc, iw, acc[j][3]);
        }
    }

    #pragma unroll
    for (int j = 0; j < 5; j++) {
        int c = cg * 10 + 2 * j;
        #pragma unroll
        for (int dd = 0; dd < 4; dd++) {
            float2 v = unpack2(acc[j][dd]);
            int d = d0 + 4 * dg + dd;
            out[((size_t)(b * CC + c))     * DD + d] = v.x;
            out[((size_t)(b * CC + c + 1)) * DD + d] = v.y;
        }
    }
}

// ---------------------------------------------------------------------------
extern "C" void kernel_launch(void* const* d_in, const int* in_sizes, int n_in,
                              void* d_out, int out_size)
{
    // inputs: [0]=batch_size (unused), [1]=img [16,1024,14,14],
    //         [2]=word [80,1024], [3]=fc_a_w [1024], [4]=fc_a_b (softmax-invariant)
    const float* img  = (const float*)d_in[1];
    const float* word = (const float*)d_in[2];
    const float* faw  = (const float*)d_in[3];
    float* out = (float*)d_out;

    const int smem1 = SMEM1_BYTES;                                // 24,704 B
    const int smem3 = (PP * 128 + PP * CC) * (int)sizeof(float);  // 163,072 B
    cudaFuncSetAttribute(scores_kernel, cudaFuncAttributeMaxDynamicSharedMemorySize, smem1);
    cudaFuncSetAttribute(out_kernel, cudaFuncAttributeMaxDynamicSharedMemorySize, smem3);

    scores_kernel<<<dim3(49, BB), 256, smem1>>>(img, word, faw);
    softmax_kernel<<<160, 256>>>();
    out_kernel<<<dim3(8, BB), 256, smem3>>>(out);
}